// round 12
// baseline (speedup 1.0000x reference)
#include <cuda_runtime.h>
#include <cuda_bf16.h>
#include <math.h>

// Problem constants
#define NSITES 1024
#define NC6 64               // 6-site codes (base table)
#define NC4 16               // 4-site tail codes (base table)
#define N12 4096             // 12-site codes: 2^12
#define NSTEPS 86            // 85 twelve-site + 1 four-site tail
// Base table (B-fragment layout, bf16x2): used by build12 + tail mirror
__device__ unsigned g_table[(NC6 + NC4) * 512];
// 12-site table in GLOBAL (L2-resident, 8.4 MB): codes 0..4095 are 12-site,
// codes 4096..4111 mirror the 4-site tail entries.
__device__ unsigned g12_table[(N12 + NC4) * 512];

// ---------------------------------------------------------------------------
// build1: 6-site (blocks 0..63) and 4-site (blocks 64..79) products,
// Y = P - I stored as bf16 B-fragments. 4-site entries also mirrored to g12.
// ---------------------------------------------------------------------------
__global__ void build_table_kernel(const float* __restrict__ A) {
    __shared__ float M[2][32][32];
    __shared__ float P[2][32][32];
    const int tid = threadIdx.x;          // 1024 threads
    const int r = tid >> 5, c = tid & 31;

    M[0][r][c] = A[r * 32 + c];
    M[1][r][c] = A[1024 + r * 32 + c];
    __syncthreads();

    const bool is6 = blockIdx.x < NC6;
    const int code = is6 ? blockIdx.x : (blockIdx.x - NC6);
    const int nsit = is6 ? 6 : 4;

    P[0][r][c] = M[code & 1][r][c];
    __syncthreads();

    int cur = 0;
    for (int t = 1; t < nsit; t++) {
        const int bsel = (code >> t) & 1;
        float acc = 0.f;
        #pragma unroll
        for (int k = 0; k < 32; k++) acc += P[cur][r][k] * M[bsel][k][c];
        P[1 - cur][r][c] = acc;
        cur ^= 1;
        __syncthreads();
    }
    if (tid < 512) {
        const int l = tid >> 4;           // lane
        const int ridx = tid & 15;        // reg 0..15
        const int tig = l & 3, g = l >> 2;
        const int kc = ridx >> 3, nt = (ridx >> 1) & 3, h = ridx & 1;
        const int row = 16 * kc + 2 * tig + 8 * h;
        const int col = 8 * nt + g;
        const float lo = P[cur][row][col]     - (row     == col ? 1.f : 0.f);
        const float hi = P[cur][row + 1][col] - (row + 1 == col ? 1.f : 0.f);
        unsigned v;
        asm("cvt.rn.bf16x2.f32 %0, %1, %2;" : "=r"(v) : "f"(hi), "f"(lo));
        const int q = ridx >> 2, j = ridx & 3;
        const int idx = q * 128 + l * 4 + j;
        g_table[blockIdx.x * 512 + idx] = v;
        if (!is6) g12_table[(N12 + code) * 512 + idx] = v;   // tail mirror
    }
}

// ---------------------------------------------------------------------------
// build2 (parallel): one 12-site entry per block, 4096 blocks x 256 threads.
// Z(ca + 64*cb) = (I+Ya)(I+Yb) - I  (fp32 product of bf16 entries).
// ---------------------------------------------------------------------------
__global__ void __launch_bounds__(256) build12_kernel() {
    __shared__ float Pa[32][32];
    __shared__ float Pb[32][33];          // padded: conflict-free column reads
    const int tid = threadIdx.x;          // 256 threads
    const int code = blockIdx.x;          // 12-bit code
    const int ca = code & 63;             // first 6 sites (low bits)
    const int cb = code >> 6;             // next 6 sites

    // Decode both 6-site entries (fragment u32 -> fp32 matrix, +I)
    #pragma unroll
    for (int i = tid; i < 512; i += 256) {
        const int l = (i >> 2) & 31, j = i & 3, q = i >> 7;
        const int rr = 4 * q + j;
        const int kc = rr >> 3, nt = (rr >> 1) & 3, h = rr & 1;
        const int tig = l & 3, g = l >> 2;
        const int row = 16 * kc + 2 * tig + 8 * h;
        const int col = 8 * nt + g;
        const unsigned ua = g_table[ca * 512 + i];
        Pa[row][col]     = __uint_as_float(ua << 16)         + (row     == col ? 1.f : 0.f);
        Pa[row + 1][col] = __uint_as_float(ua & 0xFFFF0000u) + (row + 1 == col ? 1.f : 0.f);
        const unsigned ub = g_table[cb * 512 + i];
        Pb[row][col]     = __uint_as_float(ub << 16)         + (row     == col ? 1.f : 0.f);
        Pb[row + 1][col] = __uint_as_float(ub & 0xFFFF0000u) + (row + 1 == col ? 1.f : 0.f);
    }
    __syncthreads();

    // Each thread produces 2 output u32 (indices tid, tid+256): 4 dot products
    #pragma unroll
    for (int i = tid; i < 512; i += 256) {
        const int l = (i >> 2) & 31, j = i & 3, q = i >> 7;
        const int rr = 4 * q + j;
        const int kc = rr >> 3, nt = (rr >> 1) & 3, h = rr & 1;
        const int tig = l & 3, g = l >> 2;
        const int row = 16 * kc + 2 * tig + 8 * h;
        const int col = 8 * nt + g;
        float lo = 0.f, hi = 0.f;
        #pragma unroll 8
        for (int k = 0; k < 32; k++) {
            const float bk = Pb[k][col];
            lo += Pa[row][k]     * bk;
            hi += Pa[row + 1][k] * bk;
        }
        lo -= (row     == col ? 1.f : 0.f);
        hi -= (row + 1 == col ? 1.f : 0.f);
        unsigned v;
        asm("cvt.rn.bf16x2.f32 %0, %1, %2;" : "=r"(v) : "f"(hi), "f"(lo));
        g12_table[code * 512 + i] = v;
    }
}

// ---------------------------------------------------------------------------
// Main kernel: ONE sample per warp, 28 warps/CTA, 1 CTA/SM.
// 12-site steps; B entries streamed from L2 via per-warp 3-stage cp.async ring.
// Per step:  M <- mma( bf16(M) , Z_code ) + M   ==  M @ (I + Z)   (C exact)
// ---------------------------------------------------------------------------
__device__ __forceinline__ void mma_bf16(float* d, const unsigned* a,
                                         unsigned b0, unsigned b1) {
    asm("mma.sync.aligned.m16n8k16.row.col.f32.bf16.bf16.f32 "
        "{%0,%1,%2,%3}, {%4,%5,%6,%7}, {%8,%9}, {%0,%1,%2,%3};"
        : "+f"(d[0]), "+f"(d[1]), "+f"(d[2]), "+f"(d[3])
        : "r"(a[0]), "r"(a[1]), "r"(a[2]), "r"(a[3]), "r"(b0), "r"(b1));
}

__device__ __forceinline__ void cvt_a(unsigned a[16], const float x[32]) {
    #pragma unroll
    for (int mt = 0; mt < 2; mt++)
        #pragma unroll
        for (int kc = 0; kc < 2; kc++)
            #pragma unroll
            for (int j = 0; j < 4; j++) {
                const int o = j >> 1, ih = j & 1;
                const int xi = mt * 16 + (2 * kc + o) * 4 + 2 * ih;
                asm("cvt.rn.bf16x2.f32 %0, %1, %2;"
                    : "=r"(a[mt * 8 + kc * 4 + j])
                    : "f"(x[xi + 1]), "f"(x[xi]));
            }
}

__device__ __forceinline__ void mma_half(float x[32], const unsigned a[16],
                                         int abase, uint4 ta, uint4 tb) {
    #pragma unroll
    for (int mt = 0; mt < 2; mt++) {
        const unsigned* av = a + mt * 8 + abase;
        mma_bf16(x + mt*16 + 0,  av, ta.x, ta.y);
        mma_bf16(x + mt*16 + 4,  av, ta.z, ta.w);
        mma_bf16(x + mt*16 + 8,  av, tb.x, tb.y);
        mma_bf16(x + mt*16 + 12, av, tb.z, tb.w);
    }
}

// 2KB entry -> smem stage, 16B per lane x4 chunks
__device__ __forceinline__ void prefetch_entry(unsigned dst,
                                               const unsigned* entry, int lane) {
    const unsigned* sp = entry + lane * 4;
    const unsigned dp = dst + lane * 16;
    asm volatile(
        "cp.async.cg.shared.global [%0], [%1], 16;\n\t"
        "cp.async.cg.shared.global [%2], [%3], 16;\n\t"
        "cp.async.cg.shared.global [%4], [%5], 16;\n\t"
        "cp.async.cg.shared.global [%6], [%7], 16;\n\t"
        :: "r"(dp),        "l"(sp),
           "r"(dp + 512),  "l"(sp + 128),
           "r"(dp + 1024), "l"(sp + 256),
           "r"(dp + 1536), "l"(sp + 384)
        : "memory");
}
#define CP_COMMIT()  asm volatile("cp.async.commit_group;" ::: "memory")
#define CP_WAIT1()   asm volatile("cp.async.wait_group 1;" ::: "memory")

#define NWARPS 28
#define RING_BYTES (NWARPS * 3 * 2048)        // 172 KB, 3 stages x 2KB / warp
#define MSK_BYTES (NWARPS * 32 * 4)           // 3.5 KB
#define CW_BYTES (NWARPS * 88 * 2)            // uint16 codes, padded
#define SMEM_BYTES (RING_BYTES + MSK_BYTES + CW_BYTES)
#define GRID 148
#define NTHREADS (NWARPS * 32)                // 896

__global__ void __launch_bounds__(NTHREADS, 1)
mps_kernel(const float* __restrict__ s, float* __restrict__ out) {
    extern __shared__ unsigned char smem_raw[];
    const int lane = threadIdx.x & 31;
    const int warp = threadIdx.x >> 5;
    const int b = warp * GRID + blockIdx.x;   // one sample per warp
    if (b >= 4096) return;                    // all smem is warp-private
    const int g = lane >> 2, tig = lane & 3;

    uint4* rp = reinterpret_cast<uint4*>(smem_raw + warp * 6144);
    unsigned* mw = reinterpret_cast<unsigned*>(smem_raw + RING_BYTES) + warp * 32;
    unsigned short* cw =
        reinterpret_cast<unsigned short*>(smem_raw + RING_BYTES + MSK_BYTES) + warp * 88;
    const unsigned ring_s = (unsigned)__cvta_generic_to_shared(rp);

    // Prologue: sign masks -> smem, then flat 12-bit code sequence
    {
        const float* srow = s + (size_t)b * NSITES;
        #pragma unroll 8
        for (int j = 0; j < 32; j++)
            mw[j] = __ballot_sync(0xffffffffu, srow[j * 32 + lane] > 0.f);
    }
    __syncwarp();
    for (int t = lane; t < 85; t += 32) {
        const int bit = 12 * t, w = bit >> 5, sh = bit & 31;
        const unsigned lo = mw[w];
        const unsigned hi = (w < 31) ? mw[w + 1] : 0u;
        cw[t] = (unsigned short)(__funnelshift_r(lo, hi, sh) & 0xFFFu);
    }
    if (lane == 0) {
        cw[85] = (unsigned short)(N12 + (mw[31] >> 28));   // 4-site tail
        cw[86] = 0; cw[87] = 0;
    }
    __syncwarp();

    // Init M = I in C-fragment layout
    float x[32];
    #pragma unroll
    for (int mt = 0; mt < 2; mt++)
        #pragma unroll
        for (int nt = 0; nt < 4; nt++)
            #pragma unroll
            for (int i = 0; i < 4; i++) {
                const int row = g + 8 * (i >> 1) + 16 * mt;
                const int col = 8 * nt + 2 * tig + (i & 1);
                x[mt*16 + nt*4 + i] = (row == col) ? 1.f : 0.f;
            }

    // Pipeline prologue: stages 0,1 for steps 0,1; A-fragments for step 0
    prefetch_entry(ring_s,        g12_table + (int)cw[0] * 512, lane);
    CP_COMMIT();
    prefetch_entry(ring_s + 2048, g12_table + (int)cw[1] * 512, lane);
    CP_COMMIT();
    unsigned a[16];
    cvt_a(a, x);

    int st = 0;
    for (int k = 0; k < NSTEPS; k++) {
        CP_WAIT1();                            // step k's stage is ready
        const uint4* p = rp + st * 128;
        const uint4 t0 = p[lane],      t1 = p[32 + lane];
        const uint4 t2 = p[64 + lane], t3 = p[96 + lane];
        if (k + 2 < NSTEPS) {                  // prefetch 2 ahead
            int sn = st + 2; if (sn >= 3) sn -= 3;
            prefetch_entry(ring_s + sn * 2048,
                           g12_table + (int)cw[k + 2] * 512, lane);
        }
        CP_COMMIT();                           // always (empty ok)
        mma_half(x, a, 0, t0, t1);             // kc0
        mma_half(x, a, 4, t2, t3);             // kc1
        cvt_a(a, x);                           // next step's A
        st++; if (st == 3) st = 0;
    }

    // trace(M)
    float tr = 0.f;
    #pragma unroll
    for (int mt = 0; mt < 2; mt++)
        #pragma unroll
        for (int nt = 0; nt < 4; nt++)
            #pragma unroll
            for (int i = 0; i < 4; i++) {
                const int row = g + 8 * (i >> 1) + 16 * mt;
                const int col = 8 * nt + 2 * tig + (i & 1);
                if (row == col) tr += x[mt*16 + nt*4 + i];
            }
    #pragma unroll
    for (int off = 16; off; off >>= 1)
        tr += __shfl_xor_sync(0xffffffffu, tr, off);

    if (lane == 0) out[b] = logf(tr);
}

// ---------------------------------------------------------------------------
extern "C" void kernel_launch(void* const* d_in, const int* in_sizes, int n_in,
                              void* d_out, int out_size) {
    const float* s = (const float*)d_in[0];   // [4096, 1024] fp32
    const float* A = (const float*)d_in[1];   // [2, 32, 32] fp32
    float* out = (float*)d_out;               // [4096] fp32

    static bool attr_set = false;
    if (!attr_set) {
        cudaFuncSetAttribute(mps_kernel,
                             cudaFuncAttributeMaxDynamicSharedMemorySize,
                             SMEM_BYTES);
        attr_set = true;
    }

    build_table_kernel<<<NC6 + NC4, 1024>>>(A);
    build12_kernel<<<N12, 256>>>();
    mps_kernel<<<GRID, NTHREADS, SMEM_BYTES>>>(s, out);
}

// round 13
// speedup vs baseline: 1.5938x; 1.5938x over previous
#include <cuda_runtime.h>
#include <cuda_bf16.h>
#include <math.h>

// Problem constants
#define NSITES 1024
#define NC6 64               // 6-site codes (intermediate, for 12-composition)
#define NC5 32               // 5-site codes (smem table in mps)
#define N12 4096             // 12-site codes (L2 table)
#define N12STEPS 57
#define N5STEPS 68           // 57*12 + 68*5 = 1024 exactly
// B-fragment layout per entry: 512 u32 (128 uint4)
__device__ unsigned g_table[NC6 * 512];      // 6-site (build intermediate)
__device__ unsigned g5_table[NC5 * 512];     // 5-site
__device__ unsigned g12_table[N12 * 512];    // 12-site, 8.4 MB (L2-resident)

// ---------------------------------------------------------------------------
// build1: blocks 0..63 -> 6-site products (g_table);
//         blocks 64..95 -> 5-site products (g5_table).  Y = P - I, bf16 frags.
// ---------------------------------------------------------------------------
__global__ void build_table_kernel(const float* __restrict__ A) {
    __shared__ float M[2][32][32];
    __shared__ float P[2][32][32];
    const int tid = threadIdx.x;          // 1024 threads
    const int r = tid >> 5, c = tid & 31;

    M[0][r][c] = A[r * 32 + c];
    M[1][r][c] = A[1024 + r * 32 + c];
    __syncthreads();

    const bool is6 = blockIdx.x < NC6;
    const int code = is6 ? blockIdx.x : (blockIdx.x - NC6);
    const int nsit = is6 ? 6 : 5;

    P[0][r][c] = M[code & 1][r][c];
    __syncthreads();

    int cur = 0;
    for (int t = 1; t < nsit; t++) {
        const int bsel = (code >> t) & 1;
        float acc = 0.f;
        #pragma unroll
        for (int k = 0; k < 32; k++) acc += P[cur][r][k] * M[bsel][k][c];
        P[1 - cur][r][c] = acc;
        cur ^= 1;
        __syncthreads();
    }
    if (tid < 512) {
        const int l = tid >> 4;           // lane
        const int ridx = tid & 15;        // reg 0..15
        const int tig = l & 3, g = l >> 2;
        const int kc = ridx >> 3, nt = (ridx >> 1) & 3, h = ridx & 1;
        const int row = 16 * kc + 2 * tig + 8 * h;
        const int col = 8 * nt + g;
        const float lo = P[cur][row][col]     - (row     == col ? 1.f : 0.f);
        const float hi = P[cur][row + 1][col] - (row + 1 == col ? 1.f : 0.f);
        unsigned v;
        asm("cvt.rn.bf16x2.f32 %0, %1, %2;" : "=r"(v) : "f"(hi), "f"(lo));
        const int q = ridx >> 2, j = ridx & 3;
        const int idx = q * 128 + l * 4 + j;
        if (is6) g_table[code * 512 + idx] = v;
        else     g5_table[code * 512 + idx] = v;
    }
}

// ---------------------------------------------------------------------------
// build12: one 12-site entry per block (4096 x 256).
// Z(ca + 64*cb) = (I+Ya)(I+Yb) - I. BOTH smem tiles padded -> conflict-free.
// ---------------------------------------------------------------------------
__global__ void __launch_bounds__(256) build12_kernel() {
    __shared__ float Pa[32][33];          // padded (row reads, stride-33)
    __shared__ float Pb[32][33];          // padded (column reads)
    const int tid = threadIdx.x;
    const int code = blockIdx.x;
    const int ca = code & 63;             // first 6 sites
    const int cb = code >> 6;             // next 6 sites

    #pragma unroll
    for (int i = tid; i < 512; i += 256) {
        const int l = (i >> 2) & 31, j = i & 3, q = i >> 7;
        const int rr = 4 * q + j;
        const int kc = rr >> 3, nt = (rr >> 1) & 3, h = rr & 1;
        const int tig = l & 3, g = l >> 2;
        const int row = 16 * kc + 2 * tig + 8 * h;
        const int col = 8 * nt + g;
        const unsigned ua = g_table[ca * 512 + i];
        Pa[row][col]     = __uint_as_float(ua << 16)         + (row     == col ? 1.f : 0.f);
        Pa[row + 1][col] = __uint_as_float(ua & 0xFFFF0000u) + (row + 1 == col ? 1.f : 0.f);
        const unsigned ub = g_table[cb * 512 + i];
        Pb[row][col]     = __uint_as_float(ub << 16)         + (row     == col ? 1.f : 0.f);
        Pb[row + 1][col] = __uint_as_float(ub & 0xFFFF0000u) + (row + 1 == col ? 1.f : 0.f);
    }
    __syncthreads();

    #pragma unroll
    for (int i = tid; i < 512; i += 256) {
        const int l = (i >> 2) & 31, j = i & 3, q = i >> 7;
        const int rr = 4 * q + j;
        const int kc = rr >> 3, nt = (rr >> 1) & 3, h = rr & 1;
        const int tig = l & 3, g = l >> 2;
        const int row = 16 * kc + 2 * tig + 8 * h;
        const int col = 8 * nt + g;
        float lo = 0.f, hi = 0.f;
        #pragma unroll 8
        for (int k = 0; k < 32; k++) {
            const float bk = Pb[k][col];
            lo += Pa[row][k]     * bk;
            hi += Pa[row + 1][k] * bk;
        }
        lo -= (row     == col ? 1.f : 0.f);
        hi -= (row + 1 == col ? 1.f : 0.f);
        unsigned v;
        asm("cvt.rn.bf16x2.f32 %0, %1, %2;" : "=r"(v) : "f"(hi), "f"(lo));
        g12_table[code * 512 + i] = v;
    }
}

// ---------------------------------------------------------------------------
// Main kernel: ONE sample per warp, 28 warps/CTA, 1 CTA/SM.
// Hybrid steps: alternate 12-site (B streamed from L2 via 2-stage cp.async
// ring) and 5-site (B from 64KB smem table); then 11 trailing 5-site steps.
// Per step:  M <- mma( bf16(M) , Z ) + M   ==  M @ (I + Z)   (C exact)
// ---------------------------------------------------------------------------
__device__ __forceinline__ void mma_bf16(float* d, const unsigned* a,
                                         unsigned b0, unsigned b1) {
    asm("mma.sync.aligned.m16n8k16.row.col.f32.bf16.bf16.f32 "
        "{%0,%1,%2,%3}, {%4,%5,%6,%7}, {%8,%9}, {%0,%1,%2,%3};"
        : "+f"(d[0]), "+f"(d[1]), "+f"(d[2]), "+f"(d[3])
        : "r"(a[0]), "r"(a[1]), "r"(a[2]), "r"(a[3]), "r"(b0), "r"(b1));
}

__device__ __forceinline__ void cvt_a(unsigned a[16], const float x[32]) {
    #pragma unroll
    for (int mt = 0; mt < 2; mt++)
        #pragma unroll
        for (int kc = 0; kc < 2; kc++)
            #pragma unroll
            for (int j = 0; j < 4; j++) {
                const int o = j >> 1, ih = j & 1;
                const int xi = mt * 16 + (2 * kc + o) * 4 + 2 * ih;
                asm("cvt.rn.bf16x2.f32 %0, %1, %2;"
                    : "=r"(a[mt * 8 + kc * 4 + j])
                    : "f"(x[xi + 1]), "f"(x[xi]));
            }
}

__device__ __forceinline__ void mma_half(float x[32], const unsigned a[16],
                                         int abase, uint4 ta, uint4 tb) {
    #pragma unroll
    for (int mt = 0; mt < 2; mt++) {
        const unsigned* av = a + mt * 8 + abase;
        mma_bf16(x + mt*16 + 0,  av, ta.x, ta.y);
        mma_bf16(x + mt*16 + 4,  av, ta.z, ta.w);
        mma_bf16(x + mt*16 + 8,  av, tb.x, tb.y);
        mma_bf16(x + mt*16 + 12, av, tb.z, tb.w);
    }
}

// full step from a uint4* entry base (smem), incl. next-A cvt
__device__ __forceinline__ void step_from(const uint4* p, float x[32],
                                          unsigned a[16], int lane) {
    const uint4 t0 = p[lane],      t1 = p[32 + lane];
    const uint4 t2 = p[64 + lane], t3 = p[96 + lane];
    mma_half(x, a, 0, t0, t1);
    mma_half(x, a, 4, t2, t3);
    cvt_a(a, x);
}

// 2KB entry -> smem stage, 4x cp.async 16B per lane
__device__ __forceinline__ void prefetch_entry(unsigned dst,
                                               const unsigned* entry, int lane) {
    const unsigned* sp = entry + lane * 4;
    const unsigned dp = dst + lane * 16;
    asm volatile(
        "cp.async.cg.shared.global [%0], [%1], 16;\n\t"
        "cp.async.cg.shared.global [%2], [%3], 16;\n\t"
        "cp.async.cg.shared.global [%4], [%5], 16;\n\t"
        "cp.async.cg.shared.global [%6], [%7], 16;\n\t"
        :: "r"(dp),        "l"(sp),
           "r"(dp + 512),  "l"(sp + 128),
           "r"(dp + 1024), "l"(sp + 256),
           "r"(dp + 1536), "l"(sp + 384)
        : "memory");
}
#define CP_COMMIT()  asm volatile("cp.async.commit_group;" ::: "memory")
#define CP_WAIT1()   asm volatile("cp.async.wait_group 1;" ::: "memory")

#define NWARPS 28
#define G5_BYTES (NC5 * 512 * 4)              // 64 KB
#define RING_OFF G5_BYTES
#define RING_BYTES (NWARPS * 2 * 2048)        // 112 KB, 2 stages / warp
#define MSK_OFF (RING_OFF + RING_BYTES)
#define MSK_BYTES (NWARPS * 32 * 4)           // 3.5 KB
#define CW12_OFF (MSK_OFF + MSK_BYTES)
#define CW12_BYTES (NWARPS * 64 * 2)          // 57 used, stride 64
#define CW5_OFF (CW12_OFF + CW12_BYTES)
#define CW5_BYTES (NWARPS * 72)               // 68 used, stride 72
#define SMEM_BYTES (CW5_OFF + CW5_BYTES)      // ~185 KB
#define GRID 148
#define NTHREADS (NWARPS * 32)                // 896

__global__ void __launch_bounds__(NTHREADS, 1)
mps_kernel(const float* __restrict__ s, float* __restrict__ out) {
    extern __shared__ unsigned char smem_raw[];
    uint4* g5tab = reinterpret_cast<uint4*>(smem_raw);
    const int lane = threadIdx.x & 31;
    const int warp = threadIdx.x >> 5;
    const int b = warp * GRID + blockIdx.x;   // one sample per warp
    const int g = lane >> 2, tig = lane & 3;

    {   // cooperative copy of the 5-site table (shared by all warps)
        const uint4* gt = reinterpret_cast<const uint4*>(g5_table);
        for (int i = threadIdx.x; i < NC5 * 128; i += NTHREADS)
            g5tab[i] = gt[i];
    }

    unsigned* mw = reinterpret_cast<unsigned*>(smem_raw + MSK_OFF) + warp * 32;
    unsigned short* cw12 =
        reinterpret_cast<unsigned short*>(smem_raw + CW12_OFF) + warp * 64;
    unsigned char* cw5 = smem_raw + CW5_OFF + warp * 72;

    // Prologue (warp-private): masks -> code sequences
    if (b < 4096) {
        const float* srow = s + (size_t)b * NSITES;
        #pragma unroll 8
        for (int j = 0; j < 32; j++)
            mw[j] = __ballot_sync(0xffffffffu, srow[j * 32 + lane] > 0.f);
        __syncwarp();
        // pair i: 12-bit code at bit 17i, 5-bit code at bit 17i+12
        for (int t = lane; t < N12STEPS; t += 32) {
            int bit = 17 * t, w = bit >> 5, sh = bit & 31;
            unsigned hi = (w < 31) ? mw[w + 1] : 0u;
            cw12[t] = (unsigned short)(__funnelshift_r(mw[w], hi, sh) & 0xFFFu);
            bit = 17 * t + 12; w = bit >> 5; sh = bit & 31;
            hi = (w < 31) ? mw[w + 1] : 0u;
            cw5[t] = (unsigned char)(__funnelshift_r(mw[w], hi, sh) & 31u);
        }
        // trailing 5-site codes at bits 969 + 5*(j-57)
        if (lane < N5STEPS - N12STEPS) {
            const int bit = 969 + 5 * lane, w = bit >> 5, sh = bit & 31;
            const unsigned hi = (w < 31) ? mw[w + 1] : 0u;
            cw5[N12STEPS + lane] =
                (unsigned char)(__funnelshift_r(mw[w], hi, sh) & 31u);
        }
    }
    __syncthreads();            // g5 table ready for all warps
    if (b >= 4096) return;

    uint4* rp = reinterpret_cast<uint4*>(smem_raw + RING_OFF + warp * 4096);
    const unsigned ring_s = (unsigned)__cvta_generic_to_shared(rp);

    // Init M = I in C-fragment layout
    float x[32];
    #pragma unroll
    for (int mt = 0; mt < 2; mt++)
        #pragma unroll
        for (int nt = 0; nt < 4; nt++)
            #pragma unroll
            for (int i = 0; i < 4; i++) {
                const int row = g + 8 * (i >> 1) + 16 * mt;
                const int col = 8 * nt + 2 * tig + (i & 1);
                x[mt*16 + nt*4 + i] = (row == col) ? 1.f : 0.f;
            }

    // Ring prologue: stages 0,1 hold 12-entries for steps 0,1
    prefetch_entry(ring_s,        g12_table + (int)cw12[0] * 512, lane);
    CP_COMMIT();
    prefetch_entry(ring_s + 2048, g12_table + (int)cw12[1] * 512, lane);
    CP_COMMIT();
    unsigned a[16];
    cvt_a(a, x);

    // 57 interleaved (12-site, 5-site) pairs
    for (int i = 0; i < N12STEPS; i++) {
        CP_WAIT1();                            // this 12-entry is resident
        const uint4* p = rp + (i & 1) * 128;
        const uint4 t0 = p[lane],      t1 = p[32 + lane];
        const uint4 t2 = p[64 + lane], t3 = p[96 + lane];
        if (i + 2 < N12STEPS)                  // refill the stage just freed
            prefetch_entry(ring_s + (i & 1) * 2048,
                           g12_table + (int)cw12[i + 2] * 512, lane);
        CP_COMMIT();                           // uniform group accounting
        mma_half(x, a, 0, t0, t1);             // 12-site step
        mma_half(x, a, 4, t2, t3);
        cvt_a(a, x);
        step_from(g5tab + (int)cw5[i] * 128, x, a, lane);   // 5-site step
    }
    // 11 trailing 5-site steps
    for (int j = N12STEPS; j < N5STEPS; j++)
        step_from(g5tab + (int)cw5[j] * 128, x, a, lane);

    // trace(M)
    float tr = 0.f;
    #pragma unroll
    for (int mt = 0; mt < 2; mt++)
        #pragma unroll
        for (int nt = 0; nt < 4; nt++)
            #pragma unroll
            for (int i = 0; i < 4; i++) {
                const int row = g + 8 * (i >> 1) + 16 * mt;
                const int col = 8 * nt + 2 * tig + (i & 1);
                if (row == col) tr += x[mt*16 + nt*4 + i];
            }
    #pragma unroll
    for (int off = 16; off; off >>= 1)
        tr += __shfl_xor_sync(0xffffffffu, tr, off);

    if (lane == 0) out[b] = logf(tr);
}

// ---------------------------------------------------------------------------
extern "C" void kernel_launch(void* const* d_in, const int* in_sizes, int n_in,
                              void* d_out, int out_size) {
    const float* s = (const float*)d_in[0];   // [4096, 1024] fp32
    const float* A = (const float*)d_in[1];   // [2, 32, 32] fp32
    float* out = (float*)d_out;               // [4096] fp32

    static bool attr_set = false;
    if (!attr_set) {
        cudaFuncSetAttribute(mps_kernel,
                             cudaFuncAttributeMaxDynamicSharedMemorySize,
                             SMEM_BYTES);
        attr_set = true;
    }

    build_table_kernel<<<NC6 + NC5, 1024>>>(A);
    build12_kernel<<<N12, 256>>>();
    mps_kernel<<<GRID, NTHREADS, SMEM_BYTES>>>(s, out);
}

// round 14
// speedup vs baseline: 1.8360x; 1.1520x over previous
#include <cuda_runtime.h>
#include <cuda_bf16.h>
#include <math.h>

// Problem constants
#define NSITES 1024
#define NC6 64               // 6-site codes (intermediate, for 12-composition)
#define NC5 32               // 5-site codes (smem table in mps)
#define N12 4096             // 12-site codes (L2 table)
#define N12STEPS 57
#define N5STEPS 68           // 57*12 + 68*5 = 1024 exactly
// B-fragment layout per entry: 512 u32 (128 uint4), idx = q*128 + lane*4 + j
__device__ unsigned g_table[NC6 * 512];      // 6-site, B-layout
__device__ unsigned g_tableA[NC6 * 512];     // 6-site, A-layout (for build12)
__device__ unsigned g5_table[NC5 * 512];     // 5-site, B-layout
__device__ unsigned g12_table[N12 * 512];    // 12-site, 8.4 MB (L2-resident)

// ---------------------------------------------------------------------------
// build1: blocks 0..63 -> 6-site products (B-layout g_table + A-layout copy);
//         blocks 64..95 -> 5-site products (g5_table).  Y = P - I, bf16.
// ---------------------------------------------------------------------------
__global__ void build_table_kernel(const float* __restrict__ A) {
    __shared__ float M[2][32][32];
    __shared__ float P[2][32][32];
    const int tid = threadIdx.x;          // 1024 threads
    const int r = tid >> 5, c = tid & 31;

    M[0][r][c] = A[r * 32 + c];
    M[1][r][c] = A[1024 + r * 32 + c];
    __syncthreads();

    const bool is6 = blockIdx.x < NC6;
    const int code = is6 ? blockIdx.x : (blockIdx.x - NC6);
    const int nsit = is6 ? 6 : 5;

    P[0][r][c] = M[code & 1][r][c];
    __syncthreads();

    int cur = 0;
    for (int t = 1; t < nsit; t++) {
        const int bsel = (code >> t) & 1;
        float acc = 0.f;
        #pragma unroll
        for (int k = 0; k < 32; k++) acc += P[cur][r][k] * M[bsel][k][c];
        P[1 - cur][r][c] = acc;
        cur ^= 1;
        __syncthreads();
    }
    if (tid < 512) {
        const int l = tid >> 4;           // lane
        const int ridx = tid & 15;        // reg 0..15
        const int tig = l & 3, g = l >> 2;
        const int q = ridx >> 2, j = ridx & 3;
        const int idx = q * 128 + l * 4 + j;
        {   // B-layout entry: vertical pair at (16kc+2tig+8h, 8nt+g)
            const int kc = ridx >> 3, nt = (ridx >> 1) & 3, h = ridx & 1;
            const int row = 16 * kc + 2 * tig + 8 * h;
            const int col = 8 * nt + g;
            const float lo = P[cur][row][col]     - (row     == col ? 1.f : 0.f);
            const float hi = P[cur][row + 1][col] - (row + 1 == col ? 1.f : 0.f);
            unsigned v;
            asm("cvt.rn.bf16x2.f32 %0, %1, %2;" : "=r"(v) : "f"(hi), "f"(lo));
            if (is6) g_table[code * 512 + idx] = v;
            else     g5_table[code * 512 + idx] = v;
        }
        if (is6) {  // A-layout entry: horizontal pair, reg r = mt*8+kc*4+j'
            const int mt = ridx >> 3, kc = (ridx >> 2) & 1, jj = ridx & 3;
            const int o = jj >> 1, ih = jj & 1;
            const int row = g + 8 * ih + 16 * mt;
            const int col = 8 * (2 * kc + o) + 2 * tig;
            const float lo = P[cur][row][col]     - (row == col     ? 1.f : 0.f);
            const float hi = P[cur][row][col + 1] - (row == col + 1 ? 1.f : 0.f);
            unsigned v;
            asm("cvt.rn.bf16x2.f32 %0, %1, %2;" : "=r"(v) : "f"(hi), "f"(lo));
            g_tableA[code * 512 + idx] = v;
        }
    }
}

// ---------------------------------------------------------------------------
// Shared MMA helpers (used by build12 and mps)
// ---------------------------------------------------------------------------
__device__ __forceinline__ void mma_bf16(float* d, const unsigned* a,
                                         unsigned b0, unsigned b1) {
    asm("mma.sync.aligned.m16n8k16.row.col.f32.bf16.bf16.f32 "
        "{%0,%1,%2,%3}, {%4,%5,%6,%7}, {%8,%9}, {%0,%1,%2,%3};"
        : "+f"(d[0]), "+f"(d[1]), "+f"(d[2]), "+f"(d[3])
        : "r"(a[0]), "r"(a[1]), "r"(a[2]), "r"(a[3]), "r"(b0), "r"(b1));
}

__device__ __forceinline__ void mma_half(float x[32], const unsigned a[16],
                                         int abase, uint4 ta, uint4 tb) {
    #pragma unroll
    for (int mt = 0; mt < 2; mt++) {
        const unsigned* av = a + mt * 8 + abase;
        mma_bf16(x + mt*16 + 0,  av, ta.x, ta.y);
        mma_bf16(x + mt*16 + 4,  av, ta.z, ta.w);
        mma_bf16(x + mt*16 + 8,  av, tb.x, tb.y);
        mma_bf16(x + mt*16 + 12, av, tb.z, tb.w);
    }
}

__device__ __forceinline__ void cvt_a(unsigned a[16], const float x[32]) {
    #pragma unroll
    for (int mt = 0; mt < 2; mt++)
        #pragma unroll
        for (int kc = 0; kc < 2; kc++)
            #pragma unroll
            for (int j = 0; j < 4; j++) {
                const int o = j >> 1, ih = j & 1;
                const int xi = mt * 16 + (2 * kc + o) * 4 + 2 * ih;
                asm("cvt.rn.bf16x2.f32 %0, %1, %2;"
                    : "=r"(a[mt * 8 + kc * 4 + j])
                    : "f"(x[xi + 1]), "f"(x[xi]));
            }
}

// ---------------------------------------------------------------------------
// build12 (MMA): one 12-site entry per WARP.  Z = Ya@Yb + Ya + Yb.
// Ya@Yb via 16 HMMA (fp32 acc); Ya, Yb added from A-layout entries (A-layout
// positions == C-fragment positions). Re-emitted in B-layout via smem tile.
// ---------------------------------------------------------------------------
#define B12_WARPS 8
__global__ void __launch_bounds__(B12_WARPS * 32) build12_kernel() {
    __shared__ float Zs[B12_WARPS][32 * 34];   // row-major, stride 34 (even)
    const int lane = threadIdx.x & 31;
    const int warp = threadIdx.x >> 5;
    const int code = blockIdx.x * B12_WARPS + warp;
    const int ca = code & 63;             // first 6 sites
    const int cb = code >> 6;             // next 6 sites
    const int tig = lane & 3, g = lane >> 2;
    float* zs = Zs[warp];

    // Load fragments: Ya (A-layout), Yb (B-layout), Yb (A-layout)
    unsigned a[16], ybA[16];
    {
        const uint4* pa = reinterpret_cast<const uint4*>(g_tableA + ca * 512);
        const uint4* pb = reinterpret_cast<const uint4*>(g_tableA + cb * 512);
        #pragma unroll
        for (int q = 0; q < 4; q++) {
            const uint4 va = pa[q * 32 + lane];
            a[4*q+0] = va.x; a[4*q+1] = va.y; a[4*q+2] = va.z; a[4*q+3] = va.w;
            const uint4 vb = pb[q * 32 + lane];
            ybA[4*q+0] = vb.x; ybA[4*q+1] = vb.y; ybA[4*q+2] = vb.z; ybA[4*q+3] = vb.w;
        }
    }
    const uint4* pbB = reinterpret_cast<const uint4*>(g_table + cb * 512);
    const uint4 b0 = pbB[lane],      b1 = pbB[32 + lane];
    const uint4 b2 = pbB[64 + lane], b3 = pbB[96 + lane];

    // x = Ya @ Yb (fp32 accum from 0)
    float x[32];
    #pragma unroll
    for (int i = 0; i < 32; i++) x[i] = 0.f;
    mma_half(x, a, 0, b0, b1);
    mma_half(x, a, 4, b2, b3);

    // x += Ya + Yb  (A-layout reg (mt,kc,j) covers x[xi], x[xi+1])
    #pragma unroll
    for (int ridx = 0; ridx < 16; ridx++) {
        const int mt = ridx >> 3, kc = (ridx >> 2) & 1, jj = ridx & 3;
        const int o = jj >> 1, ih = jj & 1;
        const int xi = mt * 16 + (2 * kc + o) * 4 + 2 * ih;
        const unsigned ua = a[ridx], ub = ybA[ridx];
        x[xi]     += __uint_as_float(ua << 16) + __uint_as_float(ub << 16);
        x[xi + 1] += __uint_as_float(ua & 0xFFFF0000u)
                   + __uint_as_float(ub & 0xFFFF0000u);
    }

    // Write C-layout pairs (horizontal) to smem tile
    #pragma unroll
    for (int mt = 0; mt < 2; mt++)
        #pragma unroll
        for (int nt = 0; nt < 4; nt++)
            #pragma unroll
            for (int ih = 0; ih < 2; ih++) {
                const int row = g + 8 * ih + 16 * mt;
                const int col = 8 * nt + 2 * tig;
                *reinterpret_cast<float2*>(zs + row * 34 + col) =
                    make_float2(x[mt*16 + nt*4 + 2*ih], x[mt*16 + nt*4 + 2*ih + 1]);
            }
    __syncwarp();

    // Read back in B-layout (vertical pairs), encode, store 4x STG.128
    #pragma unroll
    for (int q = 0; q < 4; q++) {
        unsigned v[4];
        #pragma unroll
        for (int j = 0; j < 4; j++) {
            const int ridx = 4 * q + j;
            const int kc = ridx >> 3, nt = (ridx >> 1) & 3, h = ridx & 1;
            const int row = 16 * kc + 2 * tig + 8 * h;
            const int col = 8 * nt + g;
            asm("cvt.rn.bf16x2.f32 %0, %1, %2;"
                : "=r"(v[j]) : "f"(zs[(row + 1) * 34 + col]), "f"(zs[row * 34 + col]));
        }
        *reinterpret_cast<uint4*>(g12_table + code * 512 + q * 128 + lane * 4) =
            make_uint4(v[0], v[1], v[2], v[3]);
    }
}

// ---------------------------------------------------------------------------
// Main kernel (UNCHANGED from R13): ONE sample per warp, 28 warps/CTA.
// Hybrid: alternate 12-site (L2-streamed, 2-stage cp.async ring) and 5-site
// (64KB smem table); then 11 trailing 5-site steps.
// ---------------------------------------------------------------------------
__device__ __forceinline__ void step_from(const uint4* p, float x[32],
                                          unsigned a[16], int lane) {
    const uint4 t0 = p[lane],      t1 = p[32 + lane];
    const uint4 t2 = p[64 + lane], t3 = p[96 + lane];
    mma_half(x, a, 0, t0, t1);
    mma_half(x, a, 4, t2, t3);
    cvt_a(a, x);
}

__device__ __forceinline__ void prefetch_entry(unsigned dst,
                                               const unsigned* entry, int lane) {
    const unsigned* sp = entry + lane * 4;
    const unsigned dp = dst + lane * 16;
    asm volatile(
        "cp.async.cg.shared.global [%0], [%1], 16;\n\t"
        "cp.async.cg.shared.global [%2], [%3], 16;\n\t"
        "cp.async.cg.shared.global [%4], [%5], 16;\n\t"
        "cp.async.cg.shared.global [%6], [%7], 16;\n\t"
        :: "r"(dp),        "l"(sp),
           "r"(dp + 512),  "l"(sp + 128),
           "r"(dp + 1024), "l"(sp + 256),
           "r"(dp + 1536), "l"(sp + 384)
        : "memory");
}
#define CP_COMMIT()  asm volatile("cp.async.commit_group;" ::: "memory")
#define CP_WAIT1()   asm volatile("cp.async.wait_group 1;" ::: "memory")

#define NWARPS 28
#define G5_BYTES (NC5 * 512 * 4)              // 64 KB
#define RING_OFF G5_BYTES
#define RING_BYTES (NWARPS * 2 * 2048)        // 112 KB, 2 stages / warp
#define MSK_OFF (RING_OFF + RING_BYTES)
#define MSK_BYTES (NWARPS * 32 * 4)           // 3.5 KB
#define CW12_OFF (MSK_OFF + MSK_BYTES)
#define CW12_BYTES (NWARPS * 64 * 2)          // 57 used, stride 64
#define CW5_OFF (CW12_OFF + CW12_BYTES)
#define CW5_BYTES (NWARPS * 72)               // 68 used, stride 72
#define SMEM_BYTES (CW5_OFF + CW5_BYTES)      // ~185 KB
#define GRID 148
#define NTHREADS (NWARPS * 32)                // 896

__global__ void __launch_bounds__(NTHREADS, 1)
mps_kernel(const float* __restrict__ s, float* __restrict__ out) {
    extern __shared__ unsigned char smem_raw[];
    uint4* g5tab = reinterpret_cast<uint4*>(smem_raw);
    const int lane = threadIdx.x & 31;
    const int warp = threadIdx.x >> 5;
    const int b = warp * GRID + blockIdx.x;   // one sample per warp
    const int g = lane >> 2, tig = lane & 3;

    {   // cooperative copy of the 5-site table (shared by all warps)
        const uint4* gt = reinterpret_cast<const uint4*>(g5_table);
        for (int i = threadIdx.x; i < NC5 * 128; i += NTHREADS)
            g5tab[i] = gt[i];
    }

    unsigned* mw = reinterpret_cast<unsigned*>(smem_raw + MSK_OFF) + warp * 32;
    unsigned short* cw12 =
        reinterpret_cast<unsigned short*>(smem_raw + CW12_OFF) + warp * 64;
    unsigned char* cw5 = smem_raw + CW5_OFF + warp * 72;

    // Prologue (warp-private): masks -> code sequences
    if (b < 4096) {
        const float* srow = s + (size_t)b * NSITES;
        #pragma unroll 8
        for (int j = 0; j < 32; j++)
            mw[j] = __ballot_sync(0xffffffffu, srow[j * 32 + lane] > 0.f);
        __syncwarp();
        // pair i: 12-bit code at bit 17i, 5-bit code at bit 17i+12
        for (int t = lane; t < N12STEPS; t += 32) {
            int bit = 17 * t, w = bit >> 5, sh = bit & 31;
            unsigned hi = (w < 31) ? mw[w + 1] : 0u;
            cw12[t] = (unsigned short)(__funnelshift_r(mw[w], hi, sh) & 0xFFFu);
            bit = 17 * t + 12; w = bit >> 5; sh = bit & 31;
            hi = (w < 31) ? mw[w + 1] : 0u;
            cw5[t] = (unsigned char)(__funnelshift_r(mw[w], hi, sh) & 31u);
        }
        // trailing 5-site codes at bits 969 + 5*(j-57)
        if (lane < N5STEPS - N12STEPS) {
            const int bit = 969 + 5 * lane, w = bit >> 5, sh = bit & 31;
            const unsigned hi = (w < 31) ? mw[w + 1] : 0u;
            cw5[N12STEPS + lane] =
                (unsigned char)(__funnelshift_r(mw[w], hi, sh) & 31u);
        }
    }
    __syncthreads();            // g5 table ready for all warps
    if (b >= 4096) return;

    uint4* rp = reinterpret_cast<uint4*>(smem_raw + RING_OFF + warp * 4096);
    const unsigned ring_s = (unsigned)__cvta_generic_to_shared(rp);

    // Init M = I in C-fragment layout
    float x[32];
    #pragma unroll
    for (int mt = 0; mt < 2; mt++)
        #pragma unroll
        for (int nt = 0; nt < 4; nt++)
            #pragma unroll
            for (int i = 0; i < 4; i++) {
                const int row = g + 8 * (i >> 1) + 16 * mt;
                const int col = 8 * nt + 2 * tig + (i & 1);
                x[mt*16 + nt*4 + i] = (row == col) ? 1.f : 0.f;
            }

    // Ring prologue: stages 0,1 hold 12-entries for steps 0,1
    prefetch_entry(ring_s,        g12_table + (int)cw12[0] * 512, lane);
    CP_COMMIT();
    prefetch_entry(ring_s + 2048, g12_table + (int)cw12[1] * 512, lane);
    CP_COMMIT();
    unsigned a[16];
    cvt_a(a, x);

    // 57 interleaved (12-site, 5-site) pairs
    for (int i = 0; i < N12STEPS; i++) {
        CP_WAIT1();                            // this 12-entry is resident
        const uint4* p = rp + (i & 1) * 128;
        const uint4 t0 = p[lane],      t1 = p[32 + lane];
        const uint4 t2 = p[64 + lane], t3 = p[96 + lane];
        if (i + 2 < N12STEPS)                  // refill the stage just freed
            prefetch_entry(ring_s + (i & 1) * 2048,
                           g12_table + (int)cw12[i + 2] * 512, lane);
        CP_COMMIT();                           // uniform group accounting
        mma_half(x, a, 0, t0, t1);             // 12-site step
        mma_half(x, a, 4, t2, t3);
        cvt_a(a, x);
        step_from(g5tab + (int)cw5[i] * 128, x, a, lane);   // 5-site step
    }
    // 11 trailing 5-site steps
    for (int j = N12STEPS; j < N5STEPS; j++)
        step_from(g5tab + (int)cw5[j] * 128, x, a, lane);

    // trace(M)
    float tr = 0.f;
    #pragma unroll
    for (int mt = 0; mt < 2; mt++)
        #pragma unroll
        for (int nt = 0; nt < 4; nt++)
            #pragma unroll
            for (int i = 0; i < 4; i++) {
                const int row = g + 8 * (i >> 1) + 16 * mt;
                const int col = 8 * nt + 2 * tig + (i & 1);
                if (row == col) tr += x[mt*16 + nt*4 + i];
            }
    #pragma unroll
    for (int off = 16; off; off >>= 1)
        tr += __shfl_xor_sync(0xffffffffu, tr, off);

    if (lane == 0) out[b] = logf(tr);
}

// ---------------------------------------------------------------------------
extern "C" void kernel_launch(void* const* d_in, const int* in_sizes, int n_in,
                              void* d_out, int out_size) {
    const float* s = (const float*)d_in[0];   // [4096, 1024] fp32
    const float* A = (const float*)d_in[1];   // [2, 32, 32] fp32
    float* out = (float*)d_out;               // [4096] fp32

    static bool attr_set = false;
    if (!attr_set) {
        cudaFuncSetAttribute(mps_kernel,
                             cudaFuncAttributeMaxDynamicSharedMemorySize,
                             SMEM_BYTES);
        attr_set = true;
    }

    build_table_kernel<<<NC6 + NC5, 1024>>>(A);
    build12_kernel<<<N12 / B12_WARPS, B12_WARPS * 32>>>();
    mps_kernel<<<GRID, NTHREADS, SMEM_BYTES>>>(s, out);
}